// round 4
// baseline (speedup 1.0000x reference)
#include <cuda_runtime.h>
#include <cstdint>
#include <cstddef>

#define Lc 1024
#define Bc 8192
#define CC 64           // steps per smem chunk
#define XPITCH 33       // padded float row pitch for xs

// epsT[i*256 + d*128 + m]
__device__ float g_epsT[Lc * 256];

__global__ void prep_eps(const float* __restrict__ eps) {
    int idx = blockIdx.x * 256 + threadIdx.x;   // idx = i*256 + dm
    int dm = idx & 255;
    int i  = idx >> 8;
    g_epsT[idx] = eps[(dm << 10) + i];          // eps[(d*128+m)*1024 + i]
}

static __device__ __forceinline__ uint64_t mul2(uint64_t a, uint64_t b) {
    uint64_t d; asm("mul.rn.f32x2 %0, %1, %2;" : "=l"(d) : "l"(a), "l"(b)); return d;
}
static __device__ __forceinline__ uint64_t fma2(uint64_t a, uint64_t b, uint64_t c) {
    uint64_t d; asm("fma.rn.f32x2 %0, %1, %2, %3;" : "=l"(d) : "l"(a), "l"(b), "l"(c)); return d;
}
static __device__ __forceinline__ float hadd2(uint64_t v) {
    float x, y; asm("mov.b64 {%0,%1}, %2;" : "=f"(x), "=f"(y) : "l"(v)); return x + y;
}
static __device__ __forceinline__ float ex2f(float x) {
    float y; asm("ex2.approx.ftz.f32 %0, %1;" : "=f"(y) : "f"(x)); return y;
}
static __device__ __forceinline__ float lg2f(float x) {
    float y; asm("lg2.approx.ftz.f32 %0, %1;" : "=f"(y) : "f"(x)); return y;
}

__global__ __launch_bounds__(256, 2)
void arqgps_main(const int* __restrict__ inputs, float* __restrict__ out) {
    extern __shared__ float smemf[];
    float* es = smemf;                           // CC*256 floats (64 KB)
    float* xs = smemf + CC * 256;                // CC*XPITCH floats (8.4 KB)

    const int t    = threadIdx.x;
    const int l    = t & 31;
    const int w    = t >> 5;            // warp 0..7
    const int wb   = w << 2;            // warp's batch base within block (4 per warp)
    const int b0   = blockIdx.x * 32;
    const int perm = (l >> 1) & 3;      // lane's slot->batch XOR key; also its term-batch

    const uint64_t ONE2 = 0x3f8000003f800000ull;

    uint64_t gx[4], gy[4];
#pragma unroll
    for (int sp = 0; sp < 4; sp++) { gx[sp] = ONE2; gy[sp] = ONE2; }

    float acc  = 0.0f;
    int   cnt0 = 0;

    for (int chunk = 0; chunk < Lc / CC; chunk++) {
        __syncthreads();
        // ---- stage epsilon chunk: natural layout es[i*256 + d*128 + m] ----
        {
            const float4* src = (const float4*)(g_epsT + chunk * (CC * 256));
            float4*       dst = (float4*)es;
#pragma unroll
            for (int it = 0; it < 16; it++)
                dst[t + it * 256] = src[t + it * 256];
        }
        // ---- stage inputs chunk as float: xs[i*XPITCH + bl] ----
        {
            int bl = t >> 3;                     // 0..31
            int i0 = (t & 7) << 3;               // 0..56 step 8
            const int* ip = inputs + (size_t)(b0 + bl) * Lc + chunk * CC + i0;
            int4 a = *(const int4*)ip;
            int4 b = *(const int4*)(ip + 4);
            int vv[8] = {a.x, a.y, a.z, a.w, b.x, b.y, b.z, b.w};
#pragma unroll
            for (int k = 0; k < 8; k++)
                xs[(i0 + k) * XPITCH + bl] = (float)vv[k];
        }
        __syncthreads();

#pragma unroll 2
        for (int ii = 0; ii < CC; ii++) {
            const int i = chunk * CC + ii;
            const float* ep = es + ii * 256;
            ulonglong2 E0 = *(const ulonglong2*)(ep + 4 * l);         // d=0, m 4l..4l+3
            ulonglong2 E1 = *(const ulonglong2*)(ep + 128 + 4 * l);   // d=1

            float v[8];
            bool  x1 = false;
#pragma unroll
            for (int sp = 0; sp < 4; sp++) {
                const int jb = sp ^ perm;                             // batch this slot tracks
                float xb = xs[ii * XPITCH + wb + jb];
                bool  p  = (xb > 0.5f);
                if (sp == 0) x1 = p;                                  // lane's term-batch x

                uint64_t p0 = fma2(E0.y, gy[sp], mul2(E0.x, gx[sp]));
                uint64_t p1 = fma2(E1.y, gy[sp], mul2(E1.x, gx[sp]));

                uint64_t Exx = p ? E1.x : E0.x;                       // SELs on ALU pipe
                uint64_t Exy = p ? E1.y : E0.y;
                gx[sp] = mul2(gx[sp], Exx);
                gy[sp] = mul2(gy[sp], Exy);

                v[2 * sp]     = hadd2(p0);
                v[2 * sp + 1] = hadd2(p1);
            }

            // XOR-permuted butterfly: slot s holds (batch (s>>1)^perm, d=s&1).
#pragma unroll
            for (int s = 0; s < 4; s++) v[s] += __shfl_xor_sync(0xffffffffu, v[s ^ 4], 4);
#pragma unroll
            for (int s = 0; s < 2; s++) v[s] += __shfl_xor_sync(0xffffffffu, v[s ^ 2], 2);
            v[0] += __shfl_xor_sync(0xffffffffu, v[0], 1);
            v[1] += __shfl_xor_sync(0xffffffffu, v[1], 1);
            v[0] += __shfl_xor_sync(0xffffffffu, v[0], 8);
            v[1] += __shfl_xor_sync(0xffffffffu, v[1], 8);
            v[0] += __shfl_xor_sync(0xffffffffu, v[0], 16);
            v[1] += __shfl_xor_sync(0xffffffffu, v[1], 16);

            const float s0 = v[0];      // lp_{d=0} of batch 'perm'
            const float s1 = v[1];      // lp_{d=1}

            const float lps = x1 ? s1 : s0;
            const float mx  = fmaxf(s0, s1);
            const float dd  = fabsf(s0 - s1);
            const float z   = ex2f(dd * -2.8853902f);                 // exp(-2*dd)
            float term = (lps - mx) - 0.34657359f * lg2f(1.0f + z);

            const int cOther = x1 ? cnt0 : (i - cnt0);                // other-spin count so far
            if (cOther >= 512) term = 0.0f;
            acc += term;
            cnt0 += x1 ? 0 : 1;
        }
    }

    if ((l & 9) == 0 && l < 8)          // lanes 0,2,4,6 -> batches 0..3 of this warp
        out[b0 + wb + (l >> 1)] = acc;
}

extern "C" void kernel_launch(void* const* d_in, const int* in_sizes, int n_in,
                              void* d_out, int out_size) {
    (void)n_in; (void)out_size;
    const int*   inputs;
    const float* eps;
    if (in_sizes[0] == Bc * Lc) {
        inputs = (const int*)d_in[0];
        eps    = (const float*)d_in[1];
    } else {
        inputs = (const int*)d_in[1];
        eps    = (const float*)d_in[0];
    }
    float* out = (float*)d_out;

    prep_eps<<<Lc, 256>>>(eps);

    size_t smem = (size_t)CC * 256 * 4 + (size_t)CC * XPITCH * 4;   // 73984 B
    cudaFuncSetAttribute(arqgps_main,
                         cudaFuncAttributeMaxDynamicSharedMemorySize, (int)smem);
    arqgps_main<<<Bc / 32, 256, smem>>>(inputs, out);
}

// round 5
// speedup vs baseline: 1.0171x; 1.0171x over previous
#include <cuda_runtime.h>
#include <cstdint>
#include <cstddef>

#define Lc 1024
#define Bc 8192

// epsT[i*256 + d*128 + m]
__device__ __align__(16) float    g_epsT[Lc * 256];
// xpack[w*Bc + b] = bitmask of inputs[b, 32w .. 32w+31]
__device__ __align__(16) uint32_t g_xpack[(Lc / 32) * Bc];

__global__ void prep_eps(const float* __restrict__ eps) {
    int idx = blockIdx.x * 256 + threadIdx.x;   // idx = i*256 + dm
    int dm = idx & 255;
    int i  = idx >> 8;
    g_epsT[idx] = eps[(dm << 10) + i];          // eps[(d*128+m)*1024 + i]
}

// one block per batch; 8 warps; each warp ballots 4 windows
__global__ void prep_x(const int* __restrict__ x) {
    int b   = blockIdx.x;
    int wid = threadIdx.x >> 5;
    int k   = threadIdx.x & 31;
#pragma unroll
    for (int r = 0; r < 4; r++) {
        int w = wid + (r << 3);
        int v = x[(size_t)b * Lc + (w << 5) + k];
        unsigned mask = __ballot_sync(0xffffffffu, v != 0);
        if (k == 0) g_xpack[w * Bc + b] = mask;
    }
}

static __device__ __forceinline__ uint64_t mul2(uint64_t a, uint64_t b) {
    uint64_t d; asm("mul.rn.f32x2 %0, %1, %2;" : "=l"(d) : "l"(a), "l"(b)); return d;
}
static __device__ __forceinline__ uint64_t fma2(uint64_t a, uint64_t b, uint64_t c) {
    uint64_t d; asm("fma.rn.f32x2 %0, %1, %2, %3;" : "=l"(d) : "l"(a), "l"(b), "l"(c)); return d;
}
static __device__ __forceinline__ float hadd2(uint64_t v) {
    float x, y; asm("mov.b64 {%0,%1}, %2;" : "=f"(x), "=f"(y) : "l"(v)); return x + y;
}
static __device__ __forceinline__ float ex2f(float x) {
    float y; asm("ex2.approx.ftz.f32 %0, %1;" : "=f"(y) : "f"(x)); return y;
}
static __device__ __forceinline__ float lg2f(float x) {
    float y; asm("lg2.approx.ftz.f32 %0, %1;" : "=f"(y) : "f"(x)); return y;
}

__global__ __launch_bounds__(32)
void arqgps_main(float* __restrict__ out) {
    const int l    = threadIdx.x;        // 32-thread blocks: 1 warp = 4 batches
    const int b0   = blockIdx.x * 4;
    const int perm = (l >> 1) & 3;       // lane's slot->batch XOR key; also its term-batch

    const uint64_t ONE2 = 0x3f8000003f800000ull;

    uint64_t gx[4], gy[4];
#pragma unroll
    for (int sp = 0; sp < 4; sp++) { gx[sp] = ONE2; gy[sp] = ONE2; }

    float acc  = 0.0f;
    int   cnt0 = 0;

    const ulonglong2* e0p = (const ulonglong2*)g_epsT + l;        // d=0, m 4l..4l+3
    const ulonglong2* e1p = e0p + 32;                             // d=1

    for (int w = 0; w < Lc / 32; w++) {
        // per-window x bitmasks, pre-permuted so xq[sp] = batch (sp^perm)
        uint32_t xq0 = __ldg(g_xpack + w * Bc + b0 + (0 ^ perm));
        uint32_t xq1 = __ldg(g_xpack + w * Bc + b0 + (1 ^ perm));
        uint32_t xq2 = __ldg(g_xpack + w * Bc + b0 + (2 ^ perm));
        uint32_t xq3 = __ldg(g_xpack + w * Bc + b0 + (3 ^ perm));

#pragma unroll 4
        for (int k = 0; k < 32; k++) {
            const int i = (w << 5) + k;
            ulonglong2 E0 = __ldg(e0p + (size_t)i * 64);
            ulonglong2 E1 = __ldg(e1p + (size_t)i * 64);

            const uint32_t bitm = 1u << k;
            const bool p0b = (xq0 & bitm) != 0;
            const bool p1b = (xq1 & bitm) != 0;
            const bool p2b = (xq2 & bitm) != 0;
            const bool p3b = (xq3 & bitm) != 0;

            float v[8];
            // slot 0
            {
                uint64_t a = fma2(E0.y, gy[0], mul2(E0.x, gx[0]));
                uint64_t b = fma2(E1.y, gy[0], mul2(E1.x, gx[0]));
                gx[0] = mul2(gx[0], p0b ? E1.x : E0.x);
                gy[0] = mul2(gy[0], p0b ? E1.y : E0.y);
                v[0] = hadd2(a); v[1] = hadd2(b);
            }
            // slot 1
            {
                uint64_t a = fma2(E0.y, gy[1], mul2(E0.x, gx[1]));
                uint64_t b = fma2(E1.y, gy[1], mul2(E1.x, gx[1]));
                gx[1] = mul2(gx[1], p1b ? E1.x : E0.x);
                gy[1] = mul2(gy[1], p1b ? E1.y : E0.y);
                v[2] = hadd2(a); v[3] = hadd2(b);
            }
            // slot 2
            {
                uint64_t a = fma2(E0.y, gy[2], mul2(E0.x, gx[2]));
                uint64_t b = fma2(E1.y, gy[2], mul2(E1.x, gx[2]));
                gx[2] = mul2(gx[2], p2b ? E1.x : E0.x);
                gy[2] = mul2(gy[2], p2b ? E1.y : E0.y);
                v[4] = hadd2(a); v[5] = hadd2(b);
            }
            // slot 3
            {
                uint64_t a = fma2(E0.y, gy[3], mul2(E0.x, gx[3]));
                uint64_t b = fma2(E1.y, gy[3], mul2(E1.x, gx[3]));
                gx[3] = mul2(gx[3], p3b ? E1.x : E0.x);
                gy[3] = mul2(gy[3], p3b ? E1.y : E0.y);
                v[6] = hadd2(a); v[7] = hadd2(b);
            }

            // XOR-permuted butterfly: slot s holds (batch (s>>1)^perm, d=s&1)
#pragma unroll
            for (int s = 0; s < 4; s++) v[s] += __shfl_xor_sync(0xffffffffu, v[s ^ 4], 4);
#pragma unroll
            for (int s = 0; s < 2; s++) v[s] += __shfl_xor_sync(0xffffffffu, v[s ^ 2], 2);
            v[0] += __shfl_xor_sync(0xffffffffu, v[0], 1);
            v[1] += __shfl_xor_sync(0xffffffffu, v[1], 1);
            v[0] += __shfl_xor_sync(0xffffffffu, v[0], 8);
            v[1] += __shfl_xor_sync(0xffffffffu, v[1], 8);
            v[0] += __shfl_xor_sync(0xffffffffu, v[0], 16);
            v[1] += __shfl_xor_sync(0xffffffffu, v[1], 16);

            const float s0 = v[0];      // lp_{d=0} of batch 'perm'
            const float s1 = v[1];      // lp_{d=1}

            const bool  x1  = p0b;      // slot 0 == lane's term batch
            const float lps = x1 ? s1 : s0;
            const float mx  = fmaxf(s0, s1);
            const float dd  = fabsf(s0 - s1);
            const float z   = ex2f(dd * -2.8853902f);              // exp(-2*dd)
            float term = (lps - mx) - 0.34657359f * lg2f(1.0f + z);

            const int cOther = x1 ? cnt0 : (i - cnt0);             // other-spin count so far
            if (cOther >= 512) term = 0.0f;
            acc += term;
            cnt0 += x1 ? 0 : 1;
        }
    }

    if (l < 8 && (l & 1) == 0)          // lanes 0,2,4,6 -> batches 0..3
        out[b0 + (l >> 1)] = acc;
}

extern "C" void kernel_launch(void* const* d_in, const int* in_sizes, int n_in,
                              void* d_out, int out_size) {
    (void)n_in; (void)out_size;
    const int*   inputs;
    const float* eps;
    if (in_sizes[0] == Bc * Lc) {
        inputs = (const int*)d_in[0];
        eps    = (const float*)d_in[1];
    } else {
        inputs = (const int*)d_in[1];
        eps    = (const float*)d_in[0];
    }
    float* out = (float*)d_out;

    prep_eps<<<Lc, 256>>>(eps);
    prep_x<<<Bc, 256>>>(inputs);

    arqgps_main<<<Bc / 4, 32>>>(out);
}

// round 6
// speedup vs baseline: 1.1055x; 1.0869x over previous
#include <cuda_runtime.h>
#include <cstdint>
#include <cstddef>

#define Lc 1024
#define Bc 8192

// epsT[i*256 + d*128 + m]
__device__ __align__(16) float    g_epsT[Lc * 256];
// xpack[w*Bc + b] = bitmask of inputs[b, 32w .. 32w+31]
__device__ __align__(16) uint32_t g_xpack[(Lc / 32) * Bc];

__global__ void prep_eps(const float* __restrict__ eps) {
    int idx = blockIdx.x * 256 + threadIdx.x;   // idx = i*256 + dm
    int dm = idx & 255;
    int i  = idx >> 8;
    g_epsT[idx] = eps[(dm << 10) + i];          // eps[(d*128+m)*1024 + i]
}

// one block per batch; 8 warps; each warp ballots 4 windows
__global__ void prep_x(const int* __restrict__ x) {
    int b   = blockIdx.x;
    int wid = threadIdx.x >> 5;
    int k   = threadIdx.x & 31;
#pragma unroll
    for (int r = 0; r < 4; r++) {
        int w = wid + (r << 3);
        int v = x[(size_t)b * Lc + (w << 5) + k];
        unsigned mask = __ballot_sync(0xffffffffu, v != 0);
        if (k == 0) g_xpack[w * Bc + b] = mask;
    }
}

static __device__ __forceinline__ uint64_t mul2(uint64_t a, uint64_t b) {
    uint64_t d; asm("mul.rn.f32x2 %0, %1, %2;" : "=l"(d) : "l"(a), "l"(b)); return d;
}
static __device__ __forceinline__ uint64_t fma2(uint64_t a, uint64_t b, uint64_t c) {
    uint64_t d; asm("fma.rn.f32x2 %0, %1, %2, %3;" : "=l"(d) : "l"(a), "l"(b), "l"(c)); return d;
}
static __device__ __forceinline__ float hadd2(uint64_t v) {
    float x, y; asm("mov.b64 {%0,%1}, %2;" : "=f"(x), "=f"(y) : "l"(v)); return x + y;
}
static __device__ __forceinline__ float ex2f(float x) {
    float y; asm("ex2.approx.ftz.f32 %0, %1;" : "=f"(y) : "f"(x)); return y;
}
static __device__ __forceinline__ float lg2f(float x) {
    float y; asm("lg2.approx.ftz.f32 %0, %1;" : "=f"(y) : "f"(x)); return y;
}

__global__ __launch_bounds__(32)
void arqgps_main(float* __restrict__ out) {
    const int l    = threadIdx.x;        // 32-thread blocks: 1 warp = 4 batches
    const int b0   = blockIdx.x * 4;
    const int perm = l & 3;              // slot sp tracks batch sp^perm; lane's term-batch = perm

    const uint64_t ONE2  = 0x3f8000003f800000ull;
    const uint64_t NEG12 = 0xbf800000bf800000ull;

    uint64_t gx[4], gy[4];
#pragma unroll
    for (int sp = 0; sp < 4; sp++) { gx[sp] = ONE2; gy[sp] = ONE2; }

    float acc  = 0.0f;
    int   cnt0 = 0;

    const ulonglong2* e0p = (const ulonglong2*)g_epsT + l;        // d=0, m 4l..4l+3
    const ulonglong2* e1p = e0p + 32;                             // d=1

    for (int w = 0; w < Lc / 32; w++) {
        // per-window x bitmasks, pre-permuted: xq[sp] = batch sp^perm
        uint32_t xq0 = __ldg(g_xpack + w * Bc + b0 + (0 ^ perm));
        uint32_t xq1 = __ldg(g_xpack + w * Bc + b0 + (1 ^ perm));
        uint32_t xq2 = __ldg(g_xpack + w * Bc + b0 + (2 ^ perm));
        uint32_t xq3 = __ldg(g_xpack + w * Bc + b0 + (3 ^ perm));

#pragma unroll 4
        for (int k = 0; k < 32; k++) {
            const int i = (w << 5) + k;
            ulonglong2 E0 = __ldg(e0p + (size_t)i * 64);
            ulonglong2 E1 = __ldg(e1p + (size_t)i * 64);

            // ED = E0 - E1 (shared across slots): delta-dot needs only this
            const uint64_t EDx = fma2(E1.x, NEG12, E0.x);
            const uint64_t EDy = fma2(E1.y, NEG12, E0.y);

            const uint32_t bitm = 1u << k;
            const bool p0b = (xq0 & bitm) != 0;
            const bool p1b = (xq1 & bitm) != 0;
            const bool p2b = (xq2 & bitm) != 0;
            const bool p3b = (xq3 & bitm) != 0;

            float v[4];
            // slot 0
            {
                uint64_t pd = fma2(EDy, gy[0], mul2(EDx, gx[0]));
                gx[0] = mul2(gx[0], p0b ? E1.x : E0.x);
                gy[0] = mul2(gy[0], p0b ? E1.y : E0.y);
                v[0] = hadd2(pd);
            }
            // slot 1
            {
                uint64_t pd = fma2(EDy, gy[1], mul2(EDx, gx[1]));
                gx[1] = mul2(gx[1], p1b ? E1.x : E0.x);
                gy[1] = mul2(gy[1], p1b ? E1.y : E0.y);
                v[1] = hadd2(pd);
            }
            // slot 2
            {
                uint64_t pd = fma2(EDy, gy[2], mul2(EDx, gx[2]));
                gx[2] = mul2(gx[2], p2b ? E1.x : E0.x);
                gy[2] = mul2(gy[2], p2b ? E1.y : E0.y);
                v[2] = hadd2(pd);
            }
            // slot 3
            {
                uint64_t pd = fma2(EDy, gy[3], mul2(EDx, gx[3]));
                gx[3] = mul2(gx[3], p3b ? E1.x : E0.x);
                gy[3] = mul2(gy[3], p3b ? E1.y : E0.y);
                v[3] = hadd2(pd);
            }

            // XOR-permuted butterfly on 4 values: slot s tracks batch s^ (l&3)
            v[0] += __shfl_xor_sync(0xffffffffu, v[2], 2);
            v[1] += __shfl_xor_sync(0xffffffffu, v[3], 2);
            v[0] += __shfl_xor_sync(0xffffffffu, v[1], 1);
            v[0] += __shfl_xor_sync(0xffffffffu, v[0], 4);
            v[0] += __shfl_xor_sync(0xffffffffu, v[0], 8);
            v[0] += __shfl_xor_sync(0xffffffffu, v[0], 16);

            const float delta = v[0];             // s0 - s1 for batch (l&3)
            const bool  x1    = p0b;              // slot0 = lane's term-batch

            // term = min(0, x1?-delta:delta) - 0.5*ln(1+exp(-2|delta|))
            const float t    = x1 ? delta : -delta;
            const float relu = fmaxf(t, 0.0f);
            const float z    = ex2f(fabsf(delta) * -2.8853902f);
            float term = -relu - 0.34657359f * lg2f(1.0f + z);

            const int cOther = x1 ? cnt0 : (i - cnt0);   // other-spin count so far
            if (cOther >= 512) term = 0.0f;
            acc += term;
            cnt0 += x1 ? 0 : 1;
        }
    }

    if (l < 4)                          // lane l -> batch b0+l
        out[b0 + l] = acc;
}

extern "C" void kernel_launch(void* const* d_in, const int* in_sizes, int n_in,
                              void* d_out, int out_size) {
    (void)n_in; (void)out_size;
    const int*   inputs;
    const float* eps;
    if (in_sizes[0] == Bc * Lc) {
        inputs = (const int*)d_in[0];
        eps    = (const float*)d_in[1];
    } else {
        inputs = (const int*)d_in[1];
        eps    = (const float*)d_in[0];
    }
    float* out = (float*)d_out;

    prep_eps<<<Lc, 256>>>(eps);
    prep_x<<<Bc, 256>>>(inputs);

    arqgps_main<<<Bc / 4, 32>>>(out);
}